// round 2
// baseline (speedup 1.0000x reference)
#include <cuda_runtime.h>

// Problem constants (from reference)
#define OUT_H      8
#define MAX_WIDTH  384
#define NUM_IMAGES 8
#define FH         160
#define FW         160
#define CCH        32
#define NUM_BOXES  256

// One float4 (4 channels) per thread; 8 threads cover one output pixel's 32
// channels (128B contiguous NHWC) -> fully coalesced gathers and stores.
// Total threads = 256*8*384*8 = 6,291,456.

__global__ __launch_bounds__(256)
void rotate_bilinear_kernel(const float* __restrict__ feat,
                            const float* __restrict__ theta,
                            const int*   __restrict__ box_info,
                            float4*      __restrict__ out)
{
    const int tid = blockIdx.x * blockDim.x + threadIdx.x;
    // tid < total guaranteed by exact grid sizing (total divisible by 256)

    const int c4    = tid & 7;        // which float4 within the 32 channels
    const int pixel = tid >> 3;       // (box, row, col)
    const int col   = pixel % MAX_WIDTH;
    const int t     = pixel / MAX_WIDTH;
    const int row   = t & (OUT_H - 1);
    const int b     = t >> 3;         // OUT_H == 8

    const int img = __ldg(&box_info[2 * b]);
    const int bw  = __ldg(&box_info[2 * b + 1]);

    float4 o = make_float4(0.f, 0.f, 0.f, 0.f);

    if (col < bw) {
        const float bwf = (float)bw;
        const float xt  = -1.0f + 2.0f * (float)col / (bwf - 1.0f);
        const float yt  = -1.0f + 2.0f * (float)row / (float)(OUT_H - 1);

        const float* th = theta + 6 * b;
        const float t0 = __ldg(th + 0), t1 = __ldg(th + 1), t2 = __ldg(th + 2);
        const float t3 = __ldg(th + 3), t4 = __ldg(th + 4), t5 = __ldg(th + 5);

        const float xs = t0 * xt + t1 * yt + t2;
        const float ys = t3 * xt + t4 * yt + t5;

        const float x = (xs + 1.0f) * ((float)FW * 0.5f);
        const float y = (ys + 1.0f) * ((float)FH * 0.5f);

        const int x0i = (int)floorf(x);
        const int y0i = (int)floorf(y);

        const int x0c = min(max(x0i,     0), FW - 1);
        const int x1c = min(max(x0i + 1, 0), FW - 1);
        const int y0c = min(max(y0i,     0), FH - 1);
        const int y1c = min(max(y0i + 1, 0), FH - 1);

        const float x0f = (float)x0c, x1f = (float)x1c;
        const float y0f = (float)y0c, y1f = (float)y1c;

        const float wa = (x1f - x) * (y1f - y);
        const float wb = (x1f - x) * (y - y0f);
        const float wc = (x - x0f) * (y1f - y);
        const float wd = (x - x0f) * (y - y0f);

        // float4-unit indices: ((img*FH + y)*FW + x) * (CCH/4) + c4
        const float4* __restrict__ f4 = (const float4*)feat;
        const int rowA = (img * FH + y0c) * FW;
        const int rowB = (img * FH + y1c) * FW;

        const float4 Ia = __ldg(f4 + (rowA + x0c) * (CCH / 4) + c4);
        const float4 Ib = __ldg(f4 + (rowB + x0c) * (CCH / 4) + c4);
        const float4 Ic = __ldg(f4 + (rowA + x1c) * (CCH / 4) + c4);
        const float4 Id = __ldg(f4 + (rowB + x1c) * (CCH / 4) + c4);

        o.x = wa * Ia.x + wb * Ib.x + wc * Ic.x + wd * Id.x;
        o.y = wa * Ia.y + wb * Ib.y + wc * Ic.y + wd * Id.y;
        o.z = wa * Ia.z + wb * Ib.z + wc * Ic.z + wd * Id.z;
        o.w = wa * Ia.w + wb * Ib.w + wc * Ic.w + wd * Id.w;
    }

    out[tid] = o;
}

extern "C" void kernel_launch(void* const* d_in, const int* in_sizes, int n_in,
                              void* d_out, int out_size)
{
    const float* feat  = (const float*)d_in[0];   // [8,160,160,32] f32
    const float* theta = (const float*)d_in[1];   // [256,6] f32
    const int*   binfo = (const int*)d_in[2];     // [256,2] i32

    const int total_threads = NUM_BOXES * OUT_H * MAX_WIDTH * (CCH / 4); // 6,291,456
    const int block = 256;
    const int grid  = total_threads / block;      // exact: 24576

    rotate_bilinear_kernel<<<grid, block>>>(feat, theta, binfo, (float4*)d_out);
}

// round 3
// speedup vs baseline: 1.1793x; 1.1793x over previous
#include <cuda_runtime.h>

#define OUT_H      8
#define MAX_WIDTH  384
#define NUM_IMAGES 8
#define FH         160
#define FW         160
#define CCH        32
#define NUM_BOXES  256

// 4 threads per output pixel; each thread handles float4 #c2 and #(c2+4)
// (offsets +0 and +64B) so each quad of lanes covers a contiguous 64B segment
// per load instruction. Scalar transform/weight math is duplicated only 4x
// per pixel (was 8x).

__global__ __launch_bounds__(256)
void rotate_bilinear_kernel(const float* __restrict__ feat,
                            const float* __restrict__ theta,
                            const int*   __restrict__ box_info,
                            float4*      __restrict__ out)
{
    const int tid = blockIdx.x * blockDim.x + threadIdx.x;

    const int c2    = tid & 3;        // float4 slot: c2 and c2+4
    const int pixel = tid >> 2;       // (box, row, col)
    const int col   = pixel % MAX_WIDTH;
    const int t     = pixel / MAX_WIDTH;
    const int row   = t & (OUT_H - 1);
    const int b     = t >> 3;         // OUT_H == 8

    const int img = __ldg(&box_info[2 * b]);
    const int bw  = __ldg(&box_info[2 * b + 1]);

    const long obase = (long)pixel * (CCH / 4) + c2;

    float4 o0 = make_float4(0.f, 0.f, 0.f, 0.f);
    float4 o1 = o0;

    if (col < bw) {
        const float xt = -1.0f + __fdividef(2.0f * (float)col, (float)bw - 1.0f);
        const float yt = -1.0f + 2.0f * (float)row * (1.0f / (float)(OUT_H - 1));

        const float* th = theta + 6 * b;
        const float t0 = __ldg(th + 0), t1 = __ldg(th + 1), t2 = __ldg(th + 2);
        const float t3 = __ldg(th + 3), t4 = __ldg(th + 4), t5 = __ldg(th + 5);

        const float xs = t0 * xt + t1 * yt + t2;
        const float ys = t3 * xt + t4 * yt + t5;

        const float x = (xs + 1.0f) * ((float)FW * 0.5f);
        const float y = (ys + 1.0f) * ((float)FH * 0.5f);

        const int x0i = (int)floorf(x);
        const int y0i = (int)floorf(y);

        const int x0c = min(max(x0i,     0), FW - 1);
        const int x1c = min(max(x0i + 1, 0), FW - 1);
        const int y0c = min(max(y0i,     0), FH - 1);
        const int y1c = min(max(y0i + 1, 0), FH - 1);

        const float x0f = (float)x0c, x1f = (float)x1c;
        const float y0f = (float)y0c, y1f = (float)y1c;

        const float wa = (x1f - x) * (y1f - y);
        const float wb = (x1f - x) * (y - y0f);
        const float wc = (x - x0f) * (y1f - y);
        const float wd = (x - x0f) * (y - y0f);

        const float4* __restrict__ f4 = (const float4*)feat;
        const int rowA = (img * FH + y0c) * FW;
        const int rowB = (img * FH + y1c) * FW;

        const int ia = (rowA + x0c) * (CCH / 4) + c2;
        const int ib = (rowB + x0c) * (CCH / 4) + c2;
        const int ic = (rowA + x1c) * (CCH / 4) + c2;
        const int id = (rowB + x1c) * (CCH / 4) + c2;

        const float4 Ia0 = __ldg(f4 + ia);
        const float4 Ib0 = __ldg(f4 + ib);
        const float4 Ic0 = __ldg(f4 + ic);
        const float4 Id0 = __ldg(f4 + id);
        const float4 Ia1 = __ldg(f4 + ia + 4);
        const float4 Ib1 = __ldg(f4 + ib + 4);
        const float4 Ic1 = __ldg(f4 + ic + 4);
        const float4 Id1 = __ldg(f4 + id + 4);

        o0.x = wa * Ia0.x + wb * Ib0.x + wc * Ic0.x + wd * Id0.x;
        o0.y = wa * Ia0.y + wb * Ib0.y + wc * Ic0.y + wd * Id0.y;
        o0.z = wa * Ia0.z + wb * Ib0.z + wc * Ic0.z + wd * Id0.z;
        o0.w = wa * Ia0.w + wb * Ib0.w + wc * Ic0.w + wd * Id0.w;

        o1.x = wa * Ia1.x + wb * Ib1.x + wc * Ic1.x + wd * Id1.x;
        o1.y = wa * Ia1.y + wb * Ib1.y + wc * Ic1.y + wd * Id1.y;
        o1.z = wa * Ia1.z + wb * Ib1.z + wc * Ic1.z + wd * Id1.z;
        o1.w = wa * Ia1.w + wb * Ib1.w + wc * Ic1.w + wd * Id1.w;
    }

    __stcs(out + obase,     o0);
    __stcs(out + obase + 4, o1);
}

extern "C" void kernel_launch(void* const* d_in, const int* in_sizes, int n_in,
                              void* d_out, int out_size)
{
    const float* feat  = (const float*)d_in[0];   // [8,160,160,32] f32
    const float* theta = (const float*)d_in[1];   // [256,6] f32
    const int*   binfo = (const int*)d_in[2];     // [256,2] i32

    const int total_threads = NUM_BOXES * OUT_H * MAX_WIDTH * (CCH / 8); // 3,145,728
    const int block = 256;
    const int grid  = total_threads / block;      // exact: 12288

    rotate_bilinear_kernel<<<grid, block>>>(feat, theta, binfo, (float4*)d_out);
}

// round 4
// speedup vs baseline: 1.2728x; 1.0793x over previous
#include <cuda_runtime.h>

#define OUT_H      8
#define MAX_WIDTH  384
#define HALF_W     192
#define NUM_IMAGES 8
#define FH         160
#define FW         160
#define CCH        32
#define NUM_BOXES  256

// 8 threads per pixel (each thread owns one float4 = 4 channels), so every
// warp gather-load covers 4 pixels x 128B contiguous = 4 L1 wavefronts.
// Each thread processes TWO pixels (col, col+192) of the same (box,row) to
// amortize scalar math and double memory-level parallelism.

__global__ __launch_bounds__(256)
void rotate_bilinear_kernel(const float* __restrict__ feat,
                            const float* __restrict__ theta,
                            const int*   __restrict__ box_info,
                            float4*      __restrict__ out)
{
    const int tid = blockIdx.x * blockDim.x + threadIdx.x;

    const int c4  = tid & 7;          // float4 slot within 32 channels
    const int p   = tid >> 3;         // (box, row, halfcol)
    const int col = p % HALF_W;       // first pixel's column; second = col+192
    const int t   = p / HALF_W;
    const int row = t & (OUT_H - 1);
    const int b   = t >> 3;           // OUT_H == 8

    const int img = __ldg(&box_info[2 * b]);
    const int bw  = __ldg(&box_info[2 * b + 1]);

    const float4* __restrict__ f4 = (const float4*)feat;

    // Per-box / per-row constants
    const float rcp2 = __fdividef(2.0f, (float)bw - 1.0f);   // 2/(bw-1)
    const float yt   = -1.0f + 2.0f * (float)row * (1.0f / (float)(OUT_H - 1));

    const float* th = theta + 6 * b;
    const float t0 = __ldg(th + 0), t1 = __ldg(th + 1), t2 = __ldg(th + 2);
    const float t3 = __ldg(th + 3), t4 = __ldg(th + 4), t5 = __ldg(th + 5);

    const float cx = t1 * yt + t2;    // x-part independent of col
    const float cy = t4 * yt + t5;

    float4 o0 = make_float4(0.f, 0.f, 0.f, 0.f);
    float4 o1 = o0;

    // ---- pixel 0: col ----
    const bool v0 = (col < bw);
    // ---- pixel 1: col + HALF_W ----
    const bool v1 = (col + HALF_W < bw);

    float w0a, w0b, w0c, w0d, w1a, w1b, w1c, w1d;
    int   i0a = 0, i0b = 0, i0c = 0, i0d = 0;
    int   i1a = 0, i1b = 0, i1c = 0, i1d = 0;

    if (v0) {
        const float xt = (float)col * rcp2 - 1.0f;
        const float x  = (t0 * xt + cx + 1.0f) * ((float)FW * 0.5f);
        const float y  = (t3 * xt + cy + 1.0f) * ((float)FH * 0.5f);
        const int x0i = (int)floorf(x), y0i = (int)floorf(y);
        const int x0c = min(max(x0i, 0), FW - 1);
        const int x1c = min(max(x0i + 1, 0), FW - 1);
        const int y0c = min(max(y0i, 0), FH - 1);
        const int y1c = min(max(y0i + 1, 0), FH - 1);
        const float dx0 = (float)x1c - x, dx1 = x - (float)x0c;
        const float dy0 = (float)y1c - y, dy1 = y - (float)y0c;
        w0a = dx0 * dy0; w0b = dx0 * dy1; w0c = dx1 * dy0; w0d = dx1 * dy1;
        const int rA = (img * FH + y0c) * FW;
        const int rB = (img * FH + y1c) * FW;
        i0a = (rA + x0c) * (CCH / 4) + c4;
        i0b = (rB + x0c) * (CCH / 4) + c4;
        i0c = (rA + x1c) * (CCH / 4) + c4;
        i0d = (rB + x1c) * (CCH / 4) + c4;
    }
    if (v1) {
        const float xt = (float)(col + HALF_W) * rcp2 - 1.0f;
        const float x  = (t0 * xt + cx + 1.0f) * ((float)FW * 0.5f);
        const float y  = (t3 * xt + cy + 1.0f) * ((float)FH * 0.5f);
        const int x0i = (int)floorf(x), y0i = (int)floorf(y);
        const int x0c = min(max(x0i, 0), FW - 1);
        const int x1c = min(max(x0i + 1, 0), FW - 1);
        const int y0c = min(max(y0i, 0), FH - 1);
        const int y1c = min(max(y0i + 1, 0), FH - 1);
        const float dx0 = (float)x1c - x, dx1 = x - (float)x0c;
        const float dy0 = (float)y1c - y, dy1 = y - (float)y0c;
        w1a = dx0 * dy0; w1b = dx0 * dy1; w1c = dx1 * dy0; w1d = dx1 * dy1;
        const int rA = (img * FH + y0c) * FW;
        const int rB = (img * FH + y1c) * FW;
        i1a = (rA + x0c) * (CCH / 4) + c4;
        i1b = (rB + x0c) * (CCH / 4) + c4;
        i1c = (rA + x1c) * (CCH / 4) + c4;
        i1d = (rB + x1c) * (CCH / 4) + c4;
    }

    // Issue all gathers before combining (max MLP)
    if (v0) {
        const float4 Ia = __ldg(f4 + i0a);
        const float4 Ib = __ldg(f4 + i0b);
        const float4 Ic = __ldg(f4 + i0c);
        const float4 Id = __ldg(f4 + i0d);
        o0.x = w0a * Ia.x + w0b * Ib.x + w0c * Ic.x + w0d * Id.x;
        o0.y = w0a * Ia.y + w0b * Ib.y + w0c * Ic.y + w0d * Id.y;
        o0.z = w0a * Ia.z + w0b * Ib.z + w0c * Ic.z + w0d * Id.z;
        o0.w = w0a * Ia.w + w0b * Ib.w + w0c * Ic.w + w0d * Id.w;
    }
    if (v1) {
        const float4 Ia = __ldg(f4 + i1a);
        const float4 Ib = __ldg(f4 + i1b);
        const float4 Ic = __ldg(f4 + i1c);
        const float4 Id = __ldg(f4 + i1d);
        o1.x = w1a * Ia.x + w1b * Ib.x + w1c * Ic.x + w1d * Id.x;
        o1.y = w1a * Ia.y + w1b * Ib.y + w1c * Ic.y + w1d * Id.y;
        o1.z = w1a * Ia.z + w1b * Ib.z + w1c * Ic.z + w1d * Id.z;
        o1.w = w1a * Ia.w + w1b * Ib.w + w1c * Ic.w + w1d * Id.w;
    }

    // Output float4 index: pixel*(CCH/4) + c4
    const long pix0 = (long)(t * MAX_WIDTH + col);
    __stcs(out + pix0 * (CCH / 4) + c4, o0);
    __stcs(out + (pix0 + HALF_W) * (CCH / 4) + c4, o1);
}

extern "C" void kernel_launch(void* const* d_in, const int* in_sizes, int n_in,
                              void* d_out, int out_size)
{
    const float* feat  = (const float*)d_in[0];   // [8,160,160,32] f32
    const float* theta = (const float*)d_in[1];   // [256,6] f32
    const int*   binfo = (const int*)d_in[2];     // [256,2] i32

    const int total_threads = NUM_BOXES * OUT_H * HALF_W * 8; // 3,145,728
    const int block = 256;
    const int grid  = total_threads / block;      // 12288

    rotate_bilinear_kernel<<<grid, block>>>(feat, theta, binfo, (float4*)d_out);
}